// round 1
// baseline (speedup 1.0000x reference)
#include <cuda_runtime.h>
#include <math.h>

// Problem constants (fixed by setup_inputs)
#define BS   8
#define HW   4096      // 64*64
#define VN   204       // hw // STEP
#define STEPV 20
#define PN   400
#define NT   128       // threads per block

// Scratch accumulators (no cudaMalloc allowed)
__device__ double g_acc[2];   // [0]=sum of loss contribs, [1]=sum of value contribs

__global__ void zero_kernel() {
    g_acc[0] = 0.0;
    g_acc[1] = 0.0;
}

__global__ __launch_bounds__(NT) void loss_kernel(
    const float* __restrict__ pred_r,     // (bs,4,h,w)
    const float* __restrict__ pred_t,     // (bs,3,h,w)
    const float* __restrict__ pred_score, // (bs,h,w)
    const float* __restrict__ gt_r,       // (bs,3,3)
    const float* __restrict__ gt_t,       // (bs,3)
    const int*   __restrict__ cls_ids,    // (bs,)
    const float* __restrict__ model)      // (bs,3,P)
{
    const int v   = blockIdx.x;
    const int b   = blockIdx.y;
    const int tid = threadIdx.x;

    const int c = cls_ids[b];
    const bool valid = (c >= 0 && c <= 29);   // (c+1) in SELECT_ID = 1..30
    if (!valid) return;                        // uniform across block
    const bool sym = (c == 12 || c == 15 || c == 18 || c == 19 || c == 20);

    __shared__ float mx[PN], my[PN], mz[PN];
    __shared__ float gx[PN], gy[PN], gz[PN];

    // gt = gt_r @ model + gt_t  (tiny, recomputed per block; data sits in L2)
    {
        const float r00 = gt_r[b*9+0], r01 = gt_r[b*9+1], r02 = gt_r[b*9+2];
        const float r10 = gt_r[b*9+3], r11 = gt_r[b*9+4], r12 = gt_r[b*9+5];
        const float r20 = gt_r[b*9+6], r21 = gt_r[b*9+7], r22 = gt_r[b*9+8];
        const float t0  = gt_t[b*3+0], t1  = gt_t[b*3+1], t2  = gt_t[b*3+2];
        const float* mb = model + (size_t)b * 3 * PN;
        for (int p = tid; p < PN; p += NT) {
            const float x = mb[p], y = mb[PN + p], z = mb[2*PN + p];
            mx[p] = x; my[p] = y; mz[p] = z;
            gx[p] = r00*x + r01*y + r02*z + t0;
            gy[p] = r10*x + r11*y + r12*z + t1;
            gz[p] = r20*x + r21*y + r22*z + t2;
        }
    }

    // Quaternion -> rotation for this view (all threads redundantly; cheap)
    const int pix = v * STEPV;
    const float* prb = pred_r + (size_t)b * 4 * HW;
    float q0 = prb[pix], q1 = prb[HW + pix], q2 = prb[2*HW + pix], q3 = prb[3*HW + pix];
    const float inv = rsqrtf(q0*q0 + q1*q1 + q2*q2 + q3*q3);
    q0 *= inv; q1 *= inv; q2 *= inv; q3 *= inv;

    const float R00 = 1.0f - 2.0f*(q2*q2 + q3*q3);
    const float R01 = 2.0f*q1*q2 - 2.0f*q0*q3;
    const float R02 = 2.0f*q0*q2 + 2.0f*q1*q3;
    const float R10 = 2.0f*q1*q2 + 2.0f*q3*q0;
    const float R11 = 1.0f - 2.0f*(q1*q1 + q3*q3);
    const float R12 = -2.0f*q0*q1 + 2.0f*q2*q3;
    const float R20 = -2.0f*q0*q2 + 2.0f*q1*q3;
    const float R21 = 2.0f*q0*q1 + 2.0f*q2*q3;
    const float R22 = 1.0f - 2.0f*(q1*q1 + q2*q2);

    const float* ptb = pred_t + (size_t)b * 3 * HW;
    const float tt0 = ptb[pix], tt1 = ptb[HW + pix], tt2 = ptb[2*HW + pix];

    __syncthreads();

    float sum = 0.0f;

    if (!sym) {
        // ADD: aligned per-point distance
        for (int p = tid; p < PN; p += NT) {
            const float x = mx[p], y = my[p], z = mz[p];
            const float dx = R00*x + R01*y + R02*z + tt0 - gx[p];
            const float dy = R10*x + R11*y + R12*z + tt1 - gy[p];
            const float dz = R20*x + R21*y + R22*z + tt2 - gz[p];
            sum += sqrtf(dx*dx + dy*dy + dz*dz);
        }
    } else {
        // ADD-S: min over all gt points. 4 pred points per thread in registers.
        float px[4], py[4], pz[4];
        bool  act[4];
        #pragma unroll
        for (int k = 0; k < 4; k++) {
            int p = tid + k * NT;
            act[k] = (p < PN);
            const int pp = act[k] ? p : tid;  // duplicate a valid point when masked
            const float x = mx[pp], y = my[pp], z = mz[pp];
            px[k] = R00*x + R01*y + R02*z + tt0;
            py[k] = R10*x + R11*y + R12*z + tt1;
            pz[k] = R20*x + R21*y + R22*z + tt2;
        }
        float mind[4] = {3.4e38f, 3.4e38f, 3.4e38f, 3.4e38f};
        #pragma unroll 4
        for (int q = 0; q < PN; q++) {
            const float ax = gx[q], ay = gy[q], az = gz[q];  // broadcast LDS
            #pragma unroll
            for (int k = 0; k < 4; k++) {
                const float dx = px[k] - ax;
                const float dy = py[k] - ay;
                const float dz = pz[k] - az;
                float d2 = dx*dx;
                d2 = fmaf(dy, dy, d2);
                d2 = fmaf(dz, dz, d2);
                mind[k] = fminf(mind[k], d2);
            }
        }
        #pragma unroll
        for (int k = 0; k < 4; k++)
            if (act[k]) sum += sqrtf(fmaxf(mind[k], 0.0f));
    }

    // Block reduction
    #pragma unroll
    for (int off = 16; off > 0; off >>= 1)
        sum += __shfl_down_sync(0xFFFFFFFFu, sum, off);
    __shared__ float red[NT / 32];
    if ((tid & 31) == 0) red[tid >> 5] = sum;
    __syncthreads();
    if (tid == 0) {
        float tot = red[0];
        #pragma unroll
        for (int w = 1; w < NT / 32; w++) tot += red[w];
        const float add_ij = tot / (float)PN;
        const float s = pred_score[(size_t)b * HW + pix];
        const double scale = 1.0 / ((double)VN * (double)BS);
        const double contrib_loss = (double)(add_ij * s - 0.01f * logf(s)) * scale;
        const double contrib_val  = (double)add_ij * scale;
        atomicAdd(&g_acc[0], contrib_loss);
        atomicAdd(&g_acc[1], contrib_val);
    }
}

__global__ void finalize_kernel(float* __restrict__ out) {
    float gl = (float)g_acc[0];
    const float gv = (float)g_acc[1];
    if (isinf(gl) || isnan(gl)) gl = 0.0f;
    out[0] = gl + 0.0f * gv;   // faithful to reference (propagates NaN if gv inf)
}

extern "C" void kernel_launch(void* const* d_in, const int* in_sizes, int n_in,
                              void* d_out, int out_size) {
    const float* pred_r     = (const float*)d_in[0];
    const float* pred_t     = (const float*)d_in[1];
    const float* pred_score = (const float*)d_in[2];
    const float* gt_r       = (const float*)d_in[3];
    const float* gt_t       = (const float*)d_in[4];
    const int*   cls_ids    = (const int*)  d_in[5];
    const float* model_xyz  = (const float*)d_in[6];
    float* out = (float*)d_out;

    zero_kernel<<<1, 1>>>();
    dim3 grid(VN, BS);
    loss_kernel<<<grid, NT>>>(pred_r, pred_t, pred_score, gt_r, gt_t, cls_ids, model_xyz);
    finalize_kernel<<<1, 1>>>(out);
}